// round 14
// baseline (speedup 1.0000x reference)
#include <cuda_runtime.h>

#define DM   64
#define DI   128
#define DS   16
#define DR   32
#define LSEQ 4096
#define NPOS 8192
#define PPB  32
#define NTH  256
#define NCTA (NPOS/PPB)
#define XSTR 72                 /* xs row stride: 16B-aligned, 8-bank offset */
#define OUT_CONV (2*DM*LSEQ)    /* 524288 floats: [2,64,64,64] conv3 output */

// ---------------- device scratch (allocation-free) ----------------
__device__ float g_rgb[NPOS*DM];
__device__ float g_dte[NPOS*DM];
__device__ float g_out[NPOS*DM];            // block output (residual stream)
__device__ float g_h  [(size_t)NPOS*DI*DS]; // 67 MB, L2-resident
__device__ float g_Ad [DI*DS];              // A = -exp(A_log), [d][s]

__device__ __forceinline__ float fsilu(float x){
    return __fdividef(x, 1.0f + __expf(-x));
}
__device__ __forceinline__ float fsoftplus(float x){
    return fmaxf(x, 0.0f) + __logf(1.0f + __expf(-fabsf(x)));
}
__device__ __forceinline__ float4 ldg4(const float* p){
    return __ldg(reinterpret_cast<const float4*>(p));
}

// ---------------- prologue: A transform only ----------------
__global__ void kPrep(const float* __restrict__ alog){
    int t = blockIdx.x*blockDim.x + threadIdx.x;
    if (t < DI*DS) g_Ad[t] = -expf(alog[t]);
}

// ---------------- prologue: 1x1 conv NCHW -> [pos][c] ----------------
__global__ __launch_bounds__(NTH) void kConvIn(const float* __restrict__ feat,
                                               const float* __restrict__ w,
                                               const float* __restrict__ bias, int tgt){
    __shared__ float fs[64*33];
    float* dst = tgt ? g_dte : g_rgb;
    int t = threadIdx.x;
    int pos0 = blockIdx.x * PPB;
    int b = pos0 >> 12, hw0 = pos0 & 4095;
    const float* fb = feat + (size_t)b*64*4096 + hw0;
    #pragma unroll
    for (int i = 0; i < 8; i++){
        int e = t + 256*i; int p = e & 31, c = e >> 5;
        fs[c*33+p] = fb[(size_t)c*4096 + p];
    }
    __syncthreads();
    int o = t & 63, pg = t >> 6;
    float acc[8];
    #pragma unroll
    for (int i = 0; i < 8; i++) acc[i] = 0.f;
    const float* wr = w + o*64;
    #pragma unroll 8
    for (int c = 0; c < 64; c++){
        float wv = __ldg(wr + c);
        #pragma unroll
        for (int i = 0; i < 8; i++) acc[i] = fmaf(wv, fs[c*33 + pg*8 + i], acc[i]);
    }
    float bv = __ldg(bias + o);
    #pragma unroll
    for (int i = 0; i < 8; i++) dst[(size_t)(pos0 + pg*8 + i)*64 + o] = acc[i] + bv;
}

// ---------------- fused per-block kernel ----------------
// 32 positions/CTA + 2-row halo recompute (rows 0..33 <-> l0-1..l0+32, rows 34/35 pad)
#define F_SMEM ((36*XSTR + 40 + 36*128 + 36*128 + 32*128 + 32*64)*4)

__global__ __launch_bounds__(NTH, 2) void kFused(int useDte, int addPrev,
                                                 const float* __restrict__ norm_w,
                                                 const float* __restrict__ ipw,   // [256][64]
                                                 const float* __restrict__ xpw,   // [64][128]
                                                 const float* __restrict__ dtw,   // [128][32]
                                                 const float* __restrict__ opw,   // [64][128]
                                                 const float* __restrict__ c3w,   // [64][64]
                                                 const float* __restrict__ c1dw,
                                                 const float* __restrict__ c1db,
                                                 const float* __restrict__ dtb,
                                                 const float* __restrict__ Dpp,
                                                 const float* __restrict__ c3b,
                                                 int firstH, int lastBlk,
                                                 float* dout, float* hExt){
    extern __shared__ float sm[];
    float* xs   = sm;                 // 36*72 normed x (halo rows)
    float* scl  = xs   + 36*XSTR;    // 40
    float* bigA = scl  + 40;         // 36*128  xc, later dels
    float* bigB = bigA + 36*128;     // 36*128  z,  later gated y
    float* xcv  = bigB + 36*128;     // 32*128  conv+silu, later obuf(32*64)
    float* dbc  = xcv  + 32*128;     // 32*64

    int t = threadIdx.x;
    int pos0 = blockIdx.x * PPB;
    int b = pos0 >> 12, l0 = pos0 & 4095;
    const float* base = useDte ? g_dte : g_rgb;
    float* hdst = hExt ? hExt : g_h;

    // ---- load x rows (halo, zero-padded) ----
    #pragma unroll
    for (int i = 0; i < 9; i++){
        int e = t + 256*i;           // e < 2304 = 36*64
        int r = e >> 6, c = e & 63;
        int lsrc = l0 - 1 + r;
        float v = 0.f;
        if (r < 34 && lsrc >= 0 && lsrc < 4096){
            size_t gi = (size_t)(b*4096 + lsrc)*64 + c;
            v = base[gi];
            if (addPrev) v += g_out[gi];
        }
        xs[r*XSTR + c] = v;
    }
    __syncthreads();
    // ---- rmsnorm scales (8 threads per row) ----
    for (int r = t >> 3; r < 36; r += 32){
        int lane8 = t & 7;
        float s = 0.f;
        #pragma unroll
        for (int j = 0; j < 8; j++){ float v = xs[r*XSTR + lane8 + 8*j]; s = fmaf(v, v, s); }
        #pragma unroll
        for (int m = 4; m >= 1; m >>= 1) s += __shfl_xor_sync(0xffffffffu, s, m);
        if (lane8 == 0) scl[r] = rsqrtf(s*(1.f/64.f) + 1e-5f);
    }
    __syncthreads();
    #pragma unroll
    for (int i = 0; i < 9; i++){
        int e = t + 256*i;
        int r = e >> 6, c = e & 63;
        xs[r*XSTR + c] = xs[r*XSTR + c] * scl[r] * __ldg(norm_w + c);
    }
    __syncthreads();

    // ---- in_proj 64 -> 256 over 36 rows (xc -> bigA, z -> bigB) ----
    {
        int ob = t & 63, pg = t >> 6;       // rows pg*9 .. pg*9+8
        float acc[4][9];
        #pragma unroll
        for (int j = 0; j < 4; j++)
            #pragma unroll
            for (int i = 0; i < 9; i++) acc[j][i] = 0.f;
        #pragma unroll 4
        for (int k4 = 0; k4 < 16; k4++){
            float4 w0 = ldg4(ipw + (ob      )*64 + k4*4);
            float4 w1 = ldg4(ipw + (ob +  64)*64 + k4*4);
            float4 w2 = ldg4(ipw + (ob + 128)*64 + k4*4);
            float4 w3 = ldg4(ipw + (ob + 192)*64 + k4*4);
            #pragma unroll
            for (int i = 0; i < 9; i++){
                float4 xv = *reinterpret_cast<const float4*>(&xs[(pg*9 + i)*XSTR + k4*4]);
                acc[0][i] = fmaf(w0.x, xv.x, acc[0][i]); acc[0][i] = fmaf(w0.y, xv.y, acc[0][i]);
                acc[0][i] = fmaf(w0.z, xv.z, acc[0][i]); acc[0][i] = fmaf(w0.w, xv.w, acc[0][i]);
                acc[1][i] = fmaf(w1.x, xv.x, acc[1][i]); acc[1][i] = fmaf(w1.y, xv.y, acc[1][i]);
                acc[1][i] = fmaf(w1.z, xv.z, acc[1][i]); acc[1][i] = fmaf(w1.w, xv.w, acc[1][i]);
                acc[2][i] = fmaf(w2.x, xv.x, acc[2][i]); acc[2][i] = fmaf(w2.y, xv.y, acc[2][i]);
                acc[2][i] = fmaf(w2.z, xv.z, acc[2][i]); acc[2][i] = fmaf(w2.w, xv.w, acc[2][i]);
                acc[3][i] = fmaf(w3.x, xv.x, acc[3][i]); acc[3][i] = fmaf(w3.y, xv.y, acc[3][i]);
                acc[3][i] = fmaf(w3.z, xv.z, acc[3][i]); acc[3][i] = fmaf(w3.w, xv.w, acc[3][i]);
            }
        }
        #pragma unroll
        for (int i = 0; i < 9; i++){
            int r = pg*9 + i;
            bigA[r*128 + ob     ] = acc[0][i];
            bigA[r*128 + ob + 64] = acc[1][i];
            bigB[r*128 + ob     ] = acc[2][i];
            bigB[r*128 + ob + 64] = acc[3][i];
        }
    }
    __syncthreads();

    // ---- depthwise conv1d + silu -> xcv ----
    {
        int d = t & 127;
        float w0 = __ldg(c1dw + d*3), w1 = __ldg(c1dw + d*3 + 1), w2 = __ldg(c1dw + d*3 + 2);
        float bv = __ldg(c1db + d);
        #pragma unroll
        for (int i = 0; i < 16; i++){
            int p = (t >> 7) + 2*i;
            float v = bv;
            v = fmaf(w0, bigA[ p   *128 + d], v);
            v = fmaf(w1, bigA[(p+1)*128 + d], v);
            v = fmaf(w2, bigA[(p+2)*128 + d], v);
            xcv[p*128 + d] = fsilu(v);
        }
    }
    __syncthreads();

    // ---- x_proj 128 -> 64 ----
    {
        int o = t & 63, pg = t >> 6;
        float acc[8];
        #pragma unroll
        for (int i = 0; i < 8; i++) acc[i] = 0.f;
        #pragma unroll 8
        for (int k4 = 0; k4 < 32; k4++){
            float4 w = ldg4(xpw + o*128 + k4*4);
            #pragma unroll
            for (int i = 0; i < 8; i++){
                float4 xv = *reinterpret_cast<const float4*>(&xcv[(pg*8 + i)*128 + k4*4]);
                acc[i] = fmaf(w.x, xv.x, acc[i]); acc[i] = fmaf(w.y, xv.y, acc[i]);
                acc[i] = fmaf(w.z, xv.z, acc[i]); acc[i] = fmaf(w.w, xv.w, acc[i]);
            }
        }
        #pragma unroll
        for (int i = 0; i < 8; i++) dbc[(pg*8 + i)*64 + o] = acc[i];
    }
    __syncthreads();

    // ---- dt_proj 32 -> 128 + softplus -> dels (reuse bigA) ----
    {
        int dl = t & 31, pg5 = t >> 5;      // p = pg5 + 8i, d = dl + 32j
        float acc[4][4];
        #pragma unroll
        for (int j = 0; j < 4; j++)
            #pragma unroll
            for (int i = 0; i < 4; i++) acc[j][i] = 0.f;
        #pragma unroll
        for (int r4 = 0; r4 < 8; r4++){
            float4 w0 = ldg4(dtw + (dl     )*32 + r4*4);
            float4 w1 = ldg4(dtw + (dl + 32)*32 + r4*4);
            float4 w2 = ldg4(dtw + (dl + 64)*32 + r4*4);
            float4 w3 = ldg4(dtw + (dl + 96)*32 + r4*4);
            #pragma unroll
            for (int i = 0; i < 4; i++){
                float4 xv = *reinterpret_cast<const float4*>(&dbc[(pg5 + 8*i)*64 + r4*4]);
                acc[0][i] = fmaf(w0.x, xv.x, acc[0][i]); acc[0][i] = fmaf(w0.y, xv.y, acc[0][i]);
                acc[0][i] = fmaf(w0.z, xv.z, acc[0][i]); acc[0][i] = fmaf(w0.w, xv.w, acc[0][i]);
                acc[1][i] = fmaf(w1.x, xv.x, acc[1][i]); acc[1][i] = fmaf(w1.y, xv.y, acc[1][i]);
                acc[1][i] = fmaf(w1.z, xv.z, acc[1][i]); acc[1][i] = fmaf(w1.w, xv.w, acc[1][i]);
                acc[2][i] = fmaf(w2.x, xv.x, acc[2][i]); acc[2][i] = fmaf(w2.y, xv.y, acc[2][i]);
                acc[2][i] = fmaf(w2.z, xv.z, acc[2][i]); acc[2][i] = fmaf(w2.w, xv.w, acc[2][i]);
                acc[3][i] = fmaf(w3.x, xv.x, acc[3][i]); acc[3][i] = fmaf(w3.y, xv.y, acc[3][i]);
                acc[3][i] = fmaf(w3.z, xv.z, acc[3][i]); acc[3][i] = fmaf(w3.w, xv.w, acc[3][i]);
            }
        }
        #pragma unroll
        for (int j = 0; j < 4; j++){
            float bv = __ldg(dtb + dl + 32*j);
            #pragma unroll
            for (int i = 0; i < 4; i++)
                bigA[(pg5 + 8*i)*128 + dl + 32*j] = fsoftplus(acc[j][i] + bv);
        }
    }
    __syncthreads();

    // ---- SSM h-update + y + gate (h prefetch pipeline) ----
    {
        int d = t & 127;
        int p0 = t >> 7;                    // tasks p = p0 + 2i
        float al[16];
        {
            const float4* Ar = reinterpret_cast<const float4*>(g_Ad + d*16);
            float4 a0 = __ldg(Ar), a1 = __ldg(Ar+1), a2 = __ldg(Ar+2), a3 = __ldg(Ar+3);
            al[0]=a0.x; al[1]=a0.y; al[2]=a0.z;  al[3]=a0.w;
            al[4]=a1.x; al[5]=a1.y; al[6]=a1.z;  al[7]=a1.w;
            al[8]=a2.x; al[9]=a2.y; al[10]=a2.z; al[11]=a2.w;
            al[12]=a3.x; al[13]=a3.y; al[14]=a3.z; al[15]=a3.w;
        }
        float dpv = __ldg(Dpp + d);
        size_t hbase = ((size_t)(pos0 + p0))*2048 + (size_t)d*16;
        const float4* hp = reinterpret_cast<const float4*>(g_h + hbase);
        float4 c0, c1, c2, c3;
        if (!firstH){ c0 = __ldg(hp); c1 = __ldg(hp+1); c2 = __ldg(hp+2); c3 = __ldg(hp+3); }
        #pragma unroll 1
        for (int i = 0; i < 16; i++){
            int p = p0 + 2*i;
            float hl[16];
            if (firstH){
                #pragma unroll
                for (int s = 0; s < 16; s++) hl[s] = 0.f;
            } else {
                hl[0]=c0.x;  hl[1]=c0.y;  hl[2]=c0.z;  hl[3]=c0.w;
                hl[4]=c1.x;  hl[5]=c1.y;  hl[6]=c1.z;  hl[7]=c1.w;
                hl[8]=c2.x;  hl[9]=c2.y;  hl[10]=c2.z; hl[11]=c2.w;
                hl[12]=c3.x; hl[13]=c3.y; hl[14]=c3.z; hl[15]=c3.w;
                if (i < 15){                // prefetch next task's h
                    const float4* hn = hp + (size_t)1024*(i+1);
                    c0 = __ldg(hn); c1 = __ldg(hn+1); c2 = __ldg(hn+2); c3 = __ldg(hn+3);
                }
            }
            float delta = bigA[p*128 + d];
            float xc    = xcv [p*128 + d];
            float dx = delta * xc;
            const float4* bm4 = reinterpret_cast<const float4*>(dbc + p*64 + 32);
            float4 b0 = bm4[0], b1 = bm4[1], b2 = bm4[2], b3 = bm4[3];
            float4 q0 = bm4[4], q1 = bm4[5], q2 = bm4[6], q3 = bm4[7];
            float bm[16] = {b0.x,b0.y,b0.z,b0.w, b1.x,b1.y,b1.z,b1.w,
                            b2.x,b2.y,b2.z,b2.w, b3.x,b3.y,b3.z,b3.w};
            float cm[16] = {q0.x,q0.y,q0.z,q0.w, q1.x,q1.y,q1.z,q1.w,
                            q2.x,q2.y,q2.z,q2.w, q3.x,q3.y,q3.z,q3.w};
            float y = 0.f;
            #pragma unroll
            for (int s = 0; s < 16; s++){
                float hn = fmaf(__expf(delta * al[s]), hl[s], dx * bm[s]);
                hl[s] = hn;
                y = fmaf(hn, cm[s], y);
            }
            float4* op = reinterpret_cast<float4*>(hdst + hbase + (size_t)4096*i);
            op[0] = make_float4(hl[0],  hl[1],  hl[2],  hl[3]);
            op[1] = make_float4(hl[4],  hl[5],  hl[6],  hl[7]);
            op[2] = make_float4(hl[8],  hl[9],  hl[10], hl[11]);
            op[3] = make_float4(hl[12], hl[13], hl[14], hl[15]);
            int zi = (p+1)*128 + d;
            float z = bigB[zi];
            bigB[zi] = fmaf(dpv, xc, y) * fsilu(z);    // gated y, in place
        }
    }
    __syncthreads();

    // ---- out_proj 128 -> 64 + residual ----
    float* obuf = xcv;   // 32*64, xcv dead
    {
        int o = t & 63, pg = t >> 6;
        float acc[8];
        #pragma unroll
        for (int i = 0; i < 8; i++) acc[i] = 0.f;
        #pragma unroll 8
        for (int d4 = 0; d4 < 32; d4++){
            float4 w = ldg4(opw + o*128 + d4*4);
            #pragma unroll
            for (int i = 0; i < 8; i++){
                float4 yv = *reinterpret_cast<const float4*>(&bigB[(pg*8 + i + 1)*128 + d4*4]);
                acc[i] = fmaf(w.x, yv.x, acc[i]); acc[i] = fmaf(w.y, yv.y, acc[i]);
                acc[i] = fmaf(w.z, yv.z, acc[i]); acc[i] = fmaf(w.w, yv.w, acc[i]);
            }
        }
        #pragma unroll
        for (int i = 0; i < 8; i++){
            int p = pg*8 + i;
            float res = acc[i] + xs[(p+1)*XSTR + o];
            if (!lastBlk) g_out[(size_t)(pos0 + p)*64 + o] = res;
            else          obuf[p*64 + o] = res;
        }
    }
    // ---- fused conv3 on last block ----
    if (lastBlk){
        __syncthreads();
        int pl = t & 31, og = t >> 5;       // o2 = og + 8j
        float acc2[8];
        #pragma unroll
        for (int j = 0; j < 8; j++) acc2[j] = 0.f;
        #pragma unroll 4
        for (int c4 = 0; c4 < 16; c4++){
            float4 xv = *reinterpret_cast<const float4*>(&obuf[pl*64 + c4*4]);
            #pragma unroll
            for (int j = 0; j < 8; j++){
                float4 w = ldg4(c3w + (og + 8*j)*64 + c4*4);
                acc2[j] = fmaf(w.x, xv.x, acc2[j]); acc2[j] = fmaf(w.y, xv.y, acc2[j]);
                acc2[j] = fmaf(w.z, xv.z, acc2[j]); acc2[j] = fmaf(w.w, xv.w, acc2[j]);
            }
        }
        #pragma unroll
        for (int j = 0; j < 8; j++){
            int o2 = og + 8*j;
            dout[(size_t)b*262144 + (size_t)o2*4096 + l0 + pl] = acc2[j] + __ldg(c3b + o2);
        }
    }
}

extern "C" void kernel_launch(void* const* d_in, const int* in_sizes, int n_in,
                              void* d_out, int out_size){
    (void)in_sizes; (void)n_in;
    const float* rgb  = (const float*)d_in[0];
    const float* dte  = (const float*)d_in[1];
    const float* c1w  = (const float*)d_in[2];
    const float* c1b  = (const float*)d_in[3];
    const float* c2w  = (const float*)d_in[4];
    const float* c2b  = (const float*)d_in[5];
    const float* c3w  = (const float*)d_in[6];
    const float* c3b  = (const float*)d_in[7];
    const float* nw   = (const float*)d_in[8];
    const float* ipw  = (const float*)d_in[9];
    const float* cdw  = (const float*)d_in[10];
    const float* cdb  = (const float*)d_in[11];
    const float* xpw  = (const float*)d_in[12];
    const float* dtw  = (const float*)d_in[13];
    const float* dtb  = (const float*)d_in[14];
    const float* alog = (const float*)d_in[15];
    const float* Dp   = (const float*)d_in[16];
    const float* opw  = (const float*)d_in[17];
    float* out = (float*)d_out;

    cudaFuncSetAttribute(kFused, cudaFuncAttributeMaxDynamicSharedMemorySize, F_SMEM);

    kPrep<<<8, 256>>>(alog);
    kConvIn<<<NCTA, NTH>>>(rgb, c1w, c1b, 0);
    kConvIn<<<NCTA, NTH>>>(dte, c2w, c2b, 1);

    // second output (final h) appended after conv output, if the harness expects it
    float* hExt = (out_size >= OUT_CONV + NPOS*DI*DS) ? (out + OUT_CONV) : nullptr;

    for (int k = 0; k < 6; k++){
        int last = (k == 5);
        kFused<<<NCTA, NTH, F_SMEM>>>(k & 1, k > 0, nw, ipw, xpw, dtw, opw, c3w,
                                      cdw, cdb, dtb, Dp, c3b,
                                      (k == 0) ? 1 : 0, last, out,
                                      last ? hExt : nullptr);
    }
}

// round 16
// speedup vs baseline: 1.5414x; 1.5414x over previous
#include <cuda_runtime.h>

#define DM   64
#define DI   128
#define DS   16
#define DR   32
#define LSEQ 4096
#define NPOS 8192
#define PPB  32
#define NTH  256
#define NCTA (NPOS/PPB)
#define XSTR 68                 /* xs row stride: 272B = 16B-aligned */
#define OUT_CONV (2*DM*LSEQ)    /* 524288 floats: [2,64,64,64] conv3 output */

// ---------------- device scratch (allocation-free) ----------------
__device__ float g_rgb[NPOS*DM];
__device__ float g_dte[NPOS*DM];
__device__ float g_out[NPOS*DM];            // block output (residual stream)
__device__ float g_h  [(size_t)NPOS*DI*DS]; // 67 MB, L2-resident
__device__ float g_Ad [DI*DS];              // A = -exp(A_log), [d][s]
// packed-transposed weights: [k4][o][4] so warp loads are coalesced LDG.128
__device__ float g_ipw4[256*64];            // [j:4][k4:16][ob:64][kk:4]
__device__ float g_xpw4[64*128];            // [k4:32][o:64][kk:4]
__device__ float g_dtw4[128*32];            // [j:4][r4:8][dl:32][rr:4]
__device__ float g_opw4[64*128];            // [d4:32][o:64][dd:4]

__device__ __forceinline__ float fsilu(float x){
    return __fdividef(x, 1.0f + __expf(-x));
}
__device__ __forceinline__ float fsoftplus(float x){
    return fmaxf(x, 0.0f) + __logf(1.0f + __expf(-fabsf(x)));
}
__device__ __forceinline__ float4 ldg4(const float* p){
    return __ldg(reinterpret_cast<const float4*>(p));
}
__device__ __forceinline__ void fma4(float& acc, float4 wv, float4 xv){
    acc = fmaf(wv.x, xv.x, acc);
    acc = fmaf(wv.y, xv.y, acc);
    acc = fmaf(wv.z, xv.z, acc);
    acc = fmaf(wv.w, xv.w, acc);
}

// ---------------- prologue: weight repack + A ----------------
__global__ void kPrep(const float* __restrict__ ipw, const float* __restrict__ xpw,
                      const float* __restrict__ dtw, const float* __restrict__ opw,
                      const float* __restrict__ alog){
    int t = blockIdx.x*blockDim.x + threadIdx.x;
    int n = gridDim.x*blockDim.x;
    for (int e = t; e < 256*64; e += n){
        int kk = e & 3, ob = (e>>2)&63, k4 = (e>>8)&15, j = e>>12;
        g_ipw4[e] = ipw[(j*64+ob)*64 + k4*4+kk];
    }
    for (int e = t; e < 64*128; e += n){
        int kk = e&3, o = (e>>2)&63, k4 = e>>8;
        g_xpw4[e] = xpw[o*128 + k4*4+kk];
    }
    for (int e = t; e < 128*32; e += n){
        int rr = e&3, dl = (e>>2)&31, r4 = (e>>7)&7, j = e>>10;
        g_dtw4[e] = dtw[(j*32+dl)*32 + r4*4+rr];
    }
    for (int e = t; e < 64*128; e += n){
        int dd = e&3, o = (e>>2)&63, d4 = e>>8;
        g_opw4[e] = opw[o*128 + d4*4+dd];
    }
    for (int e = t; e < DI*DS; e += n) g_Ad[e] = -expf(alog[e]);
}

// ---------------- prologue: 1x1 conv NCHW -> [pos][c] ----------------
__global__ __launch_bounds__(NTH) void kConvIn(const float* __restrict__ feat,
                                               const float* __restrict__ w,
                                               const float* __restrict__ bias, int tgt){
    __shared__ float fs[64*33];
    float* dst = tgt ? g_dte : g_rgb;
    int t = threadIdx.x;
    int pos0 = blockIdx.x * PPB;
    int b = pos0 >> 12, hw0 = pos0 & 4095;
    const float* fb = feat + (size_t)b*64*4096 + hw0;
    #pragma unroll
    for (int i = 0; i < 8; i++){
        int e = t + 256*i; int p = e & 31, c = e >> 5;
        fs[c*33+p] = fb[(size_t)c*4096 + p];
    }
    __syncthreads();
    int o = t & 63, pg = t >> 6;
    float acc[8];
    #pragma unroll
    for (int i = 0; i < 8; i++) acc[i] = 0.f;
    const float* wr = w + o*64;
    #pragma unroll 8
    for (int c = 0; c < 64; c++){
        float wv = __ldg(wr + c);
        #pragma unroll
        for (int i = 0; i < 8; i++) acc[i] = fmaf(wv, fs[c*33 + pg*8 + i], acc[i]);
    }
    float bv = __ldg(bias + o);
    #pragma unroll
    for (int i = 0; i < 8; i++) dst[(size_t)(pos0 + pg*8 + i)*64 + o] = acc[i] + bv;
}

// ---------------- fused per-block kernel ----------------
// 32 positions/CTA + 2-row halo recompute (rows 0..33 <-> l0-1..l0+32, rows 34/35 pad)
#define F_SMEM ((36*XSTR + 40 + 36*128 + 36*128 + 32*128 + 32*64)*4)

__global__ __launch_bounds__(NTH, 2) void kFused(int useDte, int addPrev,
                                                 const float* __restrict__ norm_w,
                                                 const float* __restrict__ c3w,   // [64][64]
                                                 const float* __restrict__ c1dw,
                                                 const float* __restrict__ c1db,
                                                 const float* __restrict__ dtb,
                                                 const float* __restrict__ Dpp,
                                                 const float* __restrict__ c3b,
                                                 int firstH, int lastBlk,
                                                 float* dout, float* hExt){
    extern __shared__ float sm[];
    float* xs   = sm;                 // 36*68 normed x (halo rows)
    float* scl  = xs   + 36*XSTR;    // 40
    float* bigA = scl  + 40;         // 36*128  xc, later dels
    float* bigB = bigA + 36*128;     // 36*128  z,  later gated y
    float* xcv  = bigB + 36*128;     // 32*128  conv+silu, later obuf(32*64)
    float* dbc  = xcv  + 32*128;     // 32*64

    int t = threadIdx.x;
    int pos0 = blockIdx.x * PPB;
    int b = pos0 >> 12, l0 = pos0 & 4095;
    const float* base = useDte ? g_dte : g_rgb;
    float* hdst = hExt ? hExt : g_h;

    // ---- load x rows (halo, zero-padded) ----
    #pragma unroll
    for (int i = 0; i < 9; i++){
        int e = t + 256*i;           // e < 2304 = 36*64
        int r = e >> 6, c = e & 63;
        int lsrc = l0 - 1 + r;
        float v = 0.f;
        if (r < 34 && lsrc >= 0 && lsrc < 4096){
            size_t gi = (size_t)(b*4096 + lsrc)*64 + c;
            v = base[gi];
            if (addPrev) v += g_out[gi];
        }
        xs[r*XSTR + c] = v;
    }
    __syncthreads();
    // ---- rmsnorm scales (8 threads per row) ----
    for (int r = t >> 3; r < 36; r += 32){
        int lane8 = t & 7;
        float s = 0.f;
        #pragma unroll
        for (int j = 0; j < 8; j++){ float v = xs[r*XSTR + lane8 + 8*j]; s = fmaf(v, v, s); }
        #pragma unroll
        for (int m = 4; m >= 1; m >>= 1) s += __shfl_xor_sync(0xffffffffu, s, m);
        if (lane8 == 0) scl[r] = rsqrtf(s*(1.f/64.f) + 1e-5f);
    }
    __syncthreads();
    #pragma unroll
    for (int i = 0; i < 9; i++){
        int e = t + 256*i;
        int r = e >> 6, c = e & 63;
        xs[r*XSTR + c] = xs[r*XSTR + c] * scl[r] * __ldg(norm_w + c);
    }
    __syncthreads();

    // ---- in_proj 64 -> 256 over 36 rows (xc -> bigA, z -> bigB) ----
    {
        int ob = t & 63, pg = t >> 6;       // rows pg*9 .. pg*9+8
        float acc[4][9];
        #pragma unroll
        for (int j = 0; j < 4; j++)
            #pragma unroll
            for (int i = 0; i < 9; i++) acc[j][i] = 0.f;
        #pragma unroll 2
        for (int k4 = 0; k4 < 16; k4++){
            float4 w0 = ldg4(g_ipw4 + (( 0 + k4)*64 + ob)*4);
            float4 w1 = ldg4(g_ipw4 + ((16 + k4)*64 + ob)*4);
            float4 w2 = ldg4(g_ipw4 + ((32 + k4)*64 + ob)*4);
            float4 w3 = ldg4(g_ipw4 + ((48 + k4)*64 + ob)*4);
            #pragma unroll
            for (int i = 0; i < 9; i++){
                float4 xv = *reinterpret_cast<const float4*>(&xs[(pg*9 + i)*XSTR + k4*4]);
                fma4(acc[0][i], w0, xv);
                fma4(acc[1][i], w1, xv);
                fma4(acc[2][i], w2, xv);
                fma4(acc[3][i], w3, xv);
            }
        }
        #pragma unroll
        for (int i = 0; i < 9; i++){
            int r = pg*9 + i;
            bigA[r*128 + ob     ] = acc[0][i];
            bigA[r*128 + ob + 64] = acc[1][i];
            bigB[r*128 + ob     ] = acc[2][i];
            bigB[r*128 + ob + 64] = acc[3][i];
        }
    }
    __syncthreads();

    // ---- depthwise conv1d + silu -> xcv ----
    {
        int d = t & 127;
        float w0 = __ldg(c1dw + d*3), w1 = __ldg(c1dw + d*3 + 1), w2 = __ldg(c1dw + d*3 + 2);
        float bv = __ldg(c1db + d);
        #pragma unroll
        for (int i = 0; i < 16; i++){
            int p = (t >> 7) + 2*i;
            float v = bv;
            v = fmaf(w0, bigA[ p   *128 + d], v);
            v = fmaf(w1, bigA[(p+1)*128 + d], v);
            v = fmaf(w2, bigA[(p+2)*128 + d], v);
            xcv[p*128 + d] = fsilu(v);
        }
    }
    __syncthreads();

    // ---- x_proj 128 -> 64 ----
    {
        int o = t & 63, pg = t >> 6;
        float acc[8];
        #pragma unroll
        for (int i = 0; i < 8; i++) acc[i] = 0.f;
        #pragma unroll 4
        for (int k4 = 0; k4 < 32; k4++){
            float4 wv = ldg4(g_xpw4 + (k4*64 + o)*4);
            #pragma unroll
            for (int i = 0; i < 8; i++){
                float4 xv = *reinterpret_cast<const float4*>(&xcv[(pg*8 + i)*128 + k4*4]);
                fma4(acc[i], wv, xv);
            }
        }
        #pragma unroll
        for (int i = 0; i < 8; i++) dbc[(pg*8 + i)*64 + o] = acc[i];
    }
    __syncthreads();

    // ---- dt_proj 32 -> 128 + softplus -> dels (reuse bigA) ----
    {
        int dl = t & 31, pg5 = t >> 5;      // p = pg5 + 8i, d = dl + 32j
        float acc[4][4];
        #pragma unroll
        for (int j = 0; j < 4; j++)
            #pragma unroll
            for (int i = 0; i < 4; i++) acc[j][i] = 0.f;
        #pragma unroll 2
        for (int r4 = 0; r4 < 8; r4++){
            float4 w0 = ldg4(g_dtw4 + (( 0 + r4)*32 + dl)*4);
            float4 w1 = ldg4(g_dtw4 + (( 8 + r4)*32 + dl)*4);
            float4 w2 = ldg4(g_dtw4 + ((16 + r4)*32 + dl)*4);
            float4 w3 = ldg4(g_dtw4 + ((24 + r4)*32 + dl)*4);
            #pragma unroll
            for (int i = 0; i < 4; i++){
                float4 xv = *reinterpret_cast<const float4*>(&dbc[(pg5 + 8*i)*64 + r4*4]);
                fma4(acc[0][i], w0, xv);
                fma4(acc[1][i], w1, xv);
                fma4(acc[2][i], w2, xv);
                fma4(acc[3][i], w3, xv);
            }
        }
        #pragma unroll
        for (int j = 0; j < 4; j++){
            float bv = __ldg(dtb + dl + 32*j);
            #pragma unroll
            for (int i = 0; i < 4; i++)
                bigA[(pg5 + 8*i)*128 + dl + 32*j] = fsoftplus(acc[j][i] + bv);
        }
    }
    __syncthreads();

    // ---- SSM h-update + y + gate (h prefetch pipeline) ----
    {
        int d = t & 127;
        int p0 = t >> 7;                    // tasks p = p0 + 2i
        float al[16];
        {
            const float4* Ar = reinterpret_cast<const float4*>(g_Ad + d*16);
            float4 a0 = __ldg(Ar), a1 = __ldg(Ar+1), a2 = __ldg(Ar+2), a3 = __ldg(Ar+3);
            al[0]=a0.x; al[1]=a0.y; al[2]=a0.z;  al[3]=a0.w;
            al[4]=a1.x; al[5]=a1.y; al[6]=a1.z;  al[7]=a1.w;
            al[8]=a2.x; al[9]=a2.y; al[10]=a2.z; al[11]=a2.w;
            al[12]=a3.x; al[13]=a3.y; al[14]=a3.z; al[15]=a3.w;
        }
        float dpv = __ldg(Dpp + d);
        size_t hbase = ((size_t)(pos0 + p0))*2048 + (size_t)d*16;
        const float4* hp = reinterpret_cast<const float4*>(g_h + hbase);
        float4 c0, c1, c2, c3;
        if (!firstH){ c0 = __ldg(hp); c1 = __ldg(hp+1); c2 = __ldg(hp+2); c3 = __ldg(hp+3); }
        #pragma unroll 1
        for (int i = 0; i < 16; i++){
            int p = p0 + 2*i;
            float hl[16];
            if (firstH){
                #pragma unroll
                for (int s = 0; s < 16; s++) hl[s] = 0.f;
            } else {
                hl[0]=c0.x;  hl[1]=c0.y;  hl[2]=c0.z;  hl[3]=c0.w;
                hl[4]=c1.x;  hl[5]=c1.y;  hl[6]=c1.z;  hl[7]=c1.w;
                hl[8]=c2.x;  hl[9]=c2.y;  hl[10]=c2.z; hl[11]=c2.w;
                hl[12]=c3.x; hl[13]=c3.y; hl[14]=c3.z; hl[15]=c3.w;
                if (i < 15){                // prefetch next task's h
                    const float4* hn = hp + (size_t)1024*(i+1);
                    c0 = __ldg(hn); c1 = __ldg(hn+1); c2 = __ldg(hn+2); c3 = __ldg(hn+3);
                }
            }
            float delta = bigA[p*128 + d];
            float xc    = xcv [p*128 + d];
            float dx = delta * xc;
            const float4* bm4 = reinterpret_cast<const float4*>(dbc + p*64 + 32);
            float4 b0 = bm4[0], b1 = bm4[1], b2 = bm4[2], b3 = bm4[3];
            float4 q0 = bm4[4], q1 = bm4[5], q2 = bm4[6], q3 = bm4[7];
            float bm[16] = {b0.x,b0.y,b0.z,b0.w, b1.x,b1.y,b1.z,b1.w,
                            b2.x,b2.y,b2.z,b2.w, b3.x,b3.y,b3.z,b3.w};
            float cm[16] = {q0.x,q0.y,q0.z,q0.w, q1.x,q1.y,q1.z,q1.w,
                            q2.x,q2.y,q2.z,q2.w, q3.x,q3.y,q3.z,q3.w};
            float y = 0.f;
            #pragma unroll
            for (int s = 0; s < 16; s++){
                float hn = fmaf(__expf(delta * al[s]), hl[s], dx * bm[s]);
                hl[s] = hn;
                y = fmaf(hn, cm[s], y);
            }
            float4* op = reinterpret_cast<float4*>(hdst + hbase + (size_t)4096*i);
            op[0] = make_float4(hl[0],  hl[1],  hl[2],  hl[3]);
            op[1] = make_float4(hl[4],  hl[5],  hl[6],  hl[7]);
            op[2] = make_float4(hl[8],  hl[9],  hl[10], hl[11]);
            op[3] = make_float4(hl[12], hl[13], hl[14], hl[15]);
            int zi = (p+1)*128 + d;
            float z = bigB[zi];
            bigB[zi] = fmaf(dpv, xc, y) * fsilu(z);    // gated y, in place
        }
    }
    __syncthreads();

    // ---- out_proj 128 -> 64 + residual ----
    float* obuf = xcv;   // 32*64, xcv dead
    {
        int o = t & 63, pg = t >> 6;
        float acc[8];
        #pragma unroll
        for (int i = 0; i < 8; i++) acc[i] = 0.f;
        #pragma unroll 4
        for (int d4 = 0; d4 < 32; d4++){
            float4 wv = ldg4(g_opw4 + (d4*64 + o)*4);
            #pragma unroll
            for (int i = 0; i < 8; i++){
                float4 yv = *reinterpret_cast<const float4*>(&bigB[(pg*8 + i + 1)*128 + d4*4]);
                fma4(acc[i], wv, yv);
            }
        }
        #pragma unroll
        for (int i = 0; i < 8; i++){
            int p = pg*8 + i;
            float res = acc[i] + xs[(p+1)*XSTR + o];
            if (!lastBlk) g_out[(size_t)(pos0 + p)*64 + o] = res;
            else          obuf[p*64 + o] = res;
        }
    }
    // ---- fused conv3 on last block ----
    if (lastBlk){
        __syncthreads();
        int pl = t & 31, og = t >> 5;       // o2 = og + 8j (uniform per warp -> broadcast ldg)
        float acc2[8];
        #pragma unroll
        for (int j = 0; j < 8; j++) acc2[j] = 0.f;
        #pragma unroll 4
        for (int c4 = 0; c4 < 16; c4++){
            float4 xv = *reinterpret_cast<const float4*>(&obuf[pl*64 + c4*4]);
            #pragma unroll
            for (int j = 0; j < 8; j++){
                float4 wv = ldg4(c3w + (og + 8*j)*64 + c4*4);
                fma4(acc2[j], wv, xv);
            }
        }
        #pragma unroll
        for (int j = 0; j < 8; j++){
            int o2 = og + 8*j;
            dout[(size_t)b*262144 + (size_t)o2*4096 + l0 + pl] = acc2[j] + __ldg(c3b + o2);
        }
    }
}

extern "C" void kernel_launch(void* const* d_in, const int* in_sizes, int n_in,
                              void* d_out, int out_size){
    (void)in_sizes; (void)n_in;
    const float* rgb  = (const float*)d_in[0];
    const float* dte  = (const float*)d_in[1];
    const float* c1w  = (const float*)d_in[2];
    const float* c1b  = (const float*)d_in[3];
    const float* c2w  = (const float*)d_in[4];
    const float* c2b  = (const float*)d_in[5];
    const float* c3w  = (const float*)d_in[6];
    const float* c3b  = (const float*)d_in[7];
    const float* nw   = (const float*)d_in[8];
    const float* ipw  = (const float*)d_in[9];
    const float* cdw  = (const float*)d_in[10];
    const float* cdb  = (const float*)d_in[11];
    const float* xpw  = (const float*)d_in[12];
    const float* dtw  = (const float*)d_in[13];
    const float* dtb  = (const float*)d_in[14];
    const float* alog = (const float*)d_in[15];
    const float* Dp   = (const float*)d_in[16];
    const float* opw  = (const float*)d_in[17];
    float* out = (float*)d_out;

    cudaFuncSetAttribute(kFused, cudaFuncAttributeMaxDynamicSharedMemorySize, F_SMEM);

    kPrep<<<64, 256>>>(ipw, xpw, dtw, opw, alog);
    kConvIn<<<NCTA, NTH>>>(rgb, c1w, c1b, 0);
    kConvIn<<<NCTA, NTH>>>(dte, c2w, c2b, 1);

    // second output (final h) appended after conv output, if the harness expects it
    float* hExt = (out_size >= OUT_CONV + NPOS*DI*DS) ? (out + OUT_CONV) : nullptr;

    for (int k = 0; k < 6; k++){
        int last = (k == 5);
        kFused<<<NCTA, NTH, F_SMEM>>>(k & 1, k > 0, nw, c3w,
                                      cdw, cdb, dtb, Dp, c3b,
                                      (k == 0) ? 1 : 0, last, out,
                                      last ? hExt : nullptr);
    }
}